// round 1
// baseline (speedup 1.0000x reference)
#include <cuda_runtime.h>
#include <math.h>

#define BB 4
#define SS 2048
#define DD 1024
#define HH 16
#define DKK 64
#define M_TOTAL (BB*SS)

// Scratch (device globals; allocation-free per harness rules)
__device__ float g_Q[BB*HH*SS*DKK];
__device__ float g_K[BB*HH*SS*DKK];
__device__ float g_V[BB*HH*SS*DKK];
__device__ float g_Ctx[BB*SS*DD];

// ---------------------------------------------------------------------------
// GEMM: C[m,n] = sum_k A[m,k] * W[n,k]   (both row-major, K contiguous)
// EPI 0: plain row-major store to Cout [M x DD]
// EPI 1: RoPE epilogue, scatter to g_Q [B,H,S,Dk]
// EPI 2: RoPE epilogue, scatter to g_K
// EPI 3: scatter to g_V (no rope)
// Tile: 128x128x16, 256 threads, 8x8 microtile.
// ---------------------------------------------------------------------------
template<int EPI>
__global__ __launch_bounds__(256)
void gemm_kernel(const float* __restrict__ A, const float* __restrict__ W,
                 float* __restrict__ Cout, const int* __restrict__ pos)
{
    __shared__ float As[16][132];
    __shared__ float Ws[16][132];

    const int tid = threadIdx.x;
    const int m0 = blockIdx.y * 128;
    const int n0 = blockIdx.x * 128;
    const int ty = tid >> 4, tx = tid & 15;
    const int row0 = ty * 8, col0 = tx * 8;

    float acc[8][8];
#pragma unroll
    for (int i = 0; i < 8; i++)
#pragma unroll
        for (int j = 0; j < 8; j++) acc[i][j] = 0.f;

    for (int k0 = 0; k0 < DD; k0 += 16) {
#pragma unroll
        for (int i = 0; i < 2; i++) {
            int idx = tid + i * 256;           // 0..511
            int r = idx >> 2;
            int k4 = (idx & 3) * 4;
            float4 v = *(const float4*)(A + (m0 + r) * DD + k0 + k4);
            As[k4 + 0][r] = v.x; As[k4 + 1][r] = v.y;
            As[k4 + 2][r] = v.z; As[k4 + 3][r] = v.w;
            float4 w = *(const float4*)(W + (n0 + r) * DD + k0 + k4);
            Ws[k4 + 0][r] = w.x; Ws[k4 + 1][r] = w.y;
            Ws[k4 + 2][r] = w.z; Ws[k4 + 3][r] = w.w;
        }
        __syncthreads();
#pragma unroll
        for (int kk = 0; kk < 16; kk++) {
            float4 a0 = *(const float4*)&As[kk][row0];
            float4 a1 = *(const float4*)&As[kk][row0 + 4];
            float4 b0 = *(const float4*)&Ws[kk][col0];
            float4 b1 = *(const float4*)&Ws[kk][col0 + 4];
            float a[8] = {a0.x, a0.y, a0.z, a0.w, a1.x, a1.y, a1.z, a1.w};
            float b[8] = {b0.x, b0.y, b0.z, b0.w, b1.x, b1.y, b1.z, b1.w};
#pragma unroll
            for (int i = 0; i < 8; i++)
#pragma unroll
                for (int j = 0; j < 8; j++)
                    acc[i][j] = fmaf(a[i], b[j], acc[i][j]);
        }
        __syncthreads();
    }

    if (EPI == 0) {
#pragma unroll
        for (int i = 0; i < 8; i++) {
            int m = m0 + row0 + i;
            float4 v0 = make_float4(acc[i][0], acc[i][1], acc[i][2], acc[i][3]);
            float4 v1 = make_float4(acc[i][4], acc[i][5], acc[i][6], acc[i][7]);
            *(float4*)(Cout + m * DD + n0 + col0)     = v0;
            *(float4*)(Cout + m * DD + n0 + col0 + 4) = v1;
        }
    } else if (EPI == 3) {
#pragma unroll
        for (int i = 0; i < 8; i++) {
            int m = m0 + row0 + i;
            int b = m >> 11;           // m / SS
            int s = m & (SS - 1);
            int e = n0 + col0;
            int h = e >> 6;
            int dk = e & 63;
            float* dst = g_V + (((b * HH + h) * SS + s) * DKK + dk);
            float4 v0 = make_float4(acc[i][0], acc[i][1], acc[i][2], acc[i][3]);
            float4 v1 = make_float4(acc[i][4], acc[i][5], acc[i][6], acc[i][7]);
            *(float4*)(dst)     = v0;
            *(float4*)(dst + 4) = v1;
        }
    } else {
        // RoPE epilogue
        const float LN_TH_OVER = 9.210340372f / 64.0f;  // ln(10000)/64
#pragma unroll
        for (int i = 0; i < 8; i++) {
            int m = m0 + row0 + i;
            int b = m >> 11;
            int s = m & (SS - 1);
            float p = (float)pos[s];
            int e = n0 + col0;
            int h = e >> 6;
            int dk0 = e & 63;
            float* dst = (EPI == 1 ? g_Q : g_K) + (((b * HH + h) * SS + s) * DKK);
            float outv[8];
#pragma unroll
            for (int j = 0; j < 8; j += 2) {
                int dk = dk0 + j;                 // even
                float inv = expf(-(float)dk * LN_TH_OVER);
                float ang = p * inv;
                float sn, cs;
                sincosf(ang, &sn, &cs);
                float x1 = acc[i][j], x2 = acc[i][j + 1];
                outv[j]     = x1 * cs - x2 * sn;
                outv[j + 1] = x1 * sn + x2 * cs;
            }
            float4 v0 = make_float4(outv[0], outv[1], outv[2], outv[3]);
            float4 v1 = make_float4(outv[4], outv[5], outv[6], outv[7]);
            *(float4*)(dst + dk0)     = v0;
            *(float4*)(dst + dk0 + 4) = v1;
        }
    }
}

// ---------------------------------------------------------------------------
// Flash attention, fp32, causal. Q-tile 128, KV-tile 64, Dk=64.
// 256 threads as 16x16; each thread: 8 rows x 4 cols for both S and O tiles.
// Dynamic smem: Qs[64][132] (d-major) | Ks[64][68] (d-major) |
//               Vs[64][68] (c-major) | Ps[64][132] (c-major)
// ---------------------------------------------------------------------------
__global__ __launch_bounds__(256)
void attn_kernel()
{
    extern __shared__ float sm[];
    float* Qs = sm;                    // 64*132
    float* Ks = Qs + 64 * 132;         // 64*68
    float* Vs = Ks + 64 * 68;          // 64*68
    float* Ps = Vs + 64 * 68;          // 64*132

    const int qt = blockIdx.x;
    const int h  = blockIdx.y;
    const int b  = blockIdx.z;
    const int tid = threadIdx.x;
    const int ty = tid >> 4, tx = tid & 15;
    const int row0 = ty * 8;
    const int c0 = tx * 4;

    const float* Q = g_Q + (size_t)(b * HH + h) * SS * DKK;
    const float* K = g_K + (size_t)(b * HH + h) * SS * DKK;
    const float* V = g_V + (size_t)(b * HH + h) * SS * DKK;

    // Load Q tile (pre-scaled by 1/sqrt(Dk) = 0.125), transposed to d-major
#pragma unroll
    for (int i = 0; i < 8; i++) {
        int idx = tid + i * 256;          // 0..2047
        int r = idx >> 4;                 // 0..127
        int k4 = (idx & 15) * 4;
        float4 v = *(const float4*)(Q + (qt * 128 + r) * DKK + k4);
        Qs[(k4 + 0) * 132 + r] = v.x * 0.125f;
        Qs[(k4 + 1) * 132 + r] = v.y * 0.125f;
        Qs[(k4 + 2) * 132 + r] = v.z * 0.125f;
        Qs[(k4 + 3) * 132 + r] = v.w * 0.125f;
    }

    float mstate[8], lstate[8], accO[8][4];
#pragma unroll
    for (int i = 0; i < 8; i++) {
        mstate[i] = -1e30f;
        lstate[i] = 0.f;
#pragma unroll
        for (int j = 0; j < 4; j++) accO[i][j] = 0.f;
    }
    __syncthreads();

    const int ktmax = qt * 2 + 1;
    for (int kt = 0; kt <= ktmax; kt++) {
        // Load K (transposed) and V (direct) tiles
#pragma unroll
        for (int i = 0; i < 4; i++) {
            int idx = tid + i * 256;      // 0..1023
            int r = idx >> 4;             // 0..63
            int k4 = (idx & 15) * 4;
            float4 kv = *(const float4*)(K + (kt * 64 + r) * DKK + k4);
            Ks[(k4 + 0) * 68 + r] = kv.x;
            Ks[(k4 + 1) * 68 + r] = kv.y;
            Ks[(k4 + 2) * 68 + r] = kv.z;
            Ks[(k4 + 3) * 68 + r] = kv.w;
            float4 vv = *(const float4*)(V + (kt * 64 + r) * DKK + k4);
            *(float4*)&Vs[r * 68 + k4] = vv;
        }
        __syncthreads();

        // S = Q K^T (scaled)
        float sacc[8][4];
#pragma unroll
        for (int i = 0; i < 8; i++)
#pragma unroll
            for (int j = 0; j < 4; j++) sacc[i][j] = 0.f;

#pragma unroll 8
        for (int d = 0; d < 64; d++) {
            float4 a0 = *(const float4*)&Qs[d * 132 + row0];
            float4 a1 = *(const float4*)&Qs[d * 132 + row0 + 4];
            float4 bb = *(const float4*)&Ks[d * 68 + c0];
            float a[8] = {a0.x, a0.y, a0.z, a0.w, a1.x, a1.y, a1.z, a1.w};
            float bv[4] = {bb.x, bb.y, bb.z, bb.w};
#pragma unroll
            for (int i = 0; i < 8; i++)
#pragma unroll
                for (int j = 0; j < 4; j++)
                    sacc[i][j] = fmaf(a[i], bv[j], sacc[i][j]);
        }

        // causal mask only needed on the two diagonal-overlapping tiles
        if (kt >= qt * 2) {
#pragma unroll
            for (int i = 0; i < 8; i++) {
                int qg = qt * 128 + row0 + i;
#pragma unroll
                for (int j = 0; j < 4; j++) {
                    int cg = kt * 64 + c0 + j;
                    if (cg > qg) sacc[i][j] = -1e30f;
                }
            }
        }

        // online softmax
        float pvals[8][4];
        float rsum[8];
#pragma unroll
        for (int i = 0; i < 8; i++) {
            float mloc = sacc[i][0];
            mloc = fmaxf(mloc, sacc[i][1]);
            mloc = fmaxf(mloc, sacc[i][2]);
            mloc = fmaxf(mloc, sacc[i][3]);
#pragma unroll
            for (int off = 1; off < 16; off <<= 1)
                mloc = fmaxf(mloc, __shfl_xor_sync(0xffffffffu, mloc, off));
            float mnew = fmaxf(mstate[i], mloc);
            float sf = __expf(mstate[i] - mnew);
            float rs = 0.f;
#pragma unroll
            for (int j = 0; j < 4; j++) {
                float pv = __expf(sacc[i][j] - mnew);
                pvals[i][j] = pv;
                rs += pv;
            }
#pragma unroll
            for (int off = 1; off < 16; off <<= 1)
                rs += __shfl_xor_sync(0xffffffffu, rs, off);
            lstate[i] = lstate[i] * sf + rs;
            mstate[i] = mnew;
#pragma unroll
            for (int j = 0; j < 4; j++) accO[i][j] *= sf;
            rsum[i] = rs; (void)rsum;
        }

        // stage P (c-major)
#pragma unroll
        for (int i = 0; i < 8; i++)
#pragma unroll
            for (int j = 0; j < 4; j++)
                Ps[(c0 + j) * 132 + row0 + i] = pvals[i][j];
        __syncthreads();

        // O += P V
#pragma unroll 8
        for (int c = 0; c < 64; c++) {
            float4 a0 = *(const float4*)&Ps[c * 132 + row0];
            float4 a1 = *(const float4*)&Ps[c * 132 + row0 + 4];
            float4 bb = *(const float4*)&Vs[c * 68 + c0];
            float a[8] = {a0.x, a0.y, a0.z, a0.w, a1.x, a1.y, a1.z, a1.w};
            float bv[4] = {bb.x, bb.y, bb.z, bb.w};
#pragma unroll
            for (int i = 0; i < 8; i++)
#pragma unroll
                for (int j = 0; j < 4; j++)
                    accO[i][j] = fmaf(a[i], bv[j], accO[i][j]);
        }
        __syncthreads();
    }

    // finalize and write context in [B,S,D] layout
#pragma unroll
    for (int i = 0; i < 8; i++) {
        float inv_l = 1.f / lstate[i];
        int s = qt * 128 + row0 + i;
        float4 v = make_float4(accO[i][0] * inv_l, accO[i][1] * inv_l,
                               accO[i][2] * inv_l, accO[i][3] * inv_l);
        *(float4*)(g_Ctx + (size_t)(b * SS + s) * DD + h * 64 + c0) = v;
    }
}

// ---------------------------------------------------------------------------
extern "C" void kernel_launch(void* const* d_in, const int* in_sizes, int n_in,
                              void* d_out, int out_size)
{
    const float* x  = (const float*)d_in[0];
    const float* Wq = (const float*)d_in[1];
    const float* Wk = (const float*)d_in[2];
    const float* Wv = (const float*)d_in[3];
    const float* Wo = (const float*)d_in[4];
    const int* pos  = (const int*)d_in[5];
    float* out = (float*)d_out;

    void* ctx_ptr = nullptr;
    cudaGetSymbolAddress(&ctx_ptr, g_Ctx);

    dim3 ggrid(DD / 128, M_TOTAL / 128);   // 8 x 64

    gemm_kernel<1><<<ggrid, 256>>>(x, Wq, nullptr, pos);
    gemm_kernel<2><<<ggrid, 256>>>(x, Wk, nullptr, pos);
    gemm_kernel<3><<<ggrid, 256>>>(x, Wv, nullptr, pos);

    static int smem_set = 0;
    const int ATTN_SMEM = (64 * 132 + 64 * 68 + 64 * 68 + 64 * 132) * 4; // 102400
    if (!smem_set) {
        cudaFuncSetAttribute(attn_kernel,
                             cudaFuncAttributeMaxDynamicSharedMemorySize,
                             ATTN_SMEM);
        smem_set = 1;
    }
    dim3 agrid(SS / 128, HH, BB);
    attn_kernel<<<agrid, 256, ATTN_SMEM>>>();

    gemm_kernel<0><<<ggrid, 256>>>((const float*)ctx_ptr, Wo, out, pos);
}

// round 2
// speedup vs baseline: 1.6788x; 1.6788x over previous
#include <cuda_runtime.h>
#include <math.h>
#include <stdint.h>

#define BB 4
#define SS 2048
#define DD 1024
#define HH 16
#define DKK 64
#define M_TOTAL (BB*SS)

// Scratch (device globals; allocation-free per harness rules)
__device__ float g_Q[BB*HH*SS*DKK];
__device__ float g_K[BB*HH*SS*DKK];
__device__ float g_V[BB*HH*SS*DKK];
__device__ float g_Ctx[BB*SS*DD];

// ---------------------------------------------------------------------------
// helpers
// ---------------------------------------------------------------------------
__device__ __forceinline__ uint32_t f2tf(float x) {
    uint32_t r;
    asm("cvt.rna.tf32.f32 %0, %1;" : "=r"(r) : "f"(x));
    return r;
}

__device__ __forceinline__ void mma_tf32(float* c, const uint32_t* a, const uint32_t* b) {
    asm volatile(
        "mma.sync.aligned.m16n8k8.row.col.f32.tf32.tf32.f32 "
        "{%0,%1,%2,%3},{%4,%5,%6,%7},{%8,%9},{%0,%1,%2,%3};"
        : "+f"(c[0]), "+f"(c[1]), "+f"(c[2]), "+f"(c[3])
        : "r"(a[0]), "r"(a[1]), "r"(a[2]), "r"(a[3]), "r"(b[0]), "r"(b[1]));
}

__device__ __forceinline__ void cp16(void* smem, const void* g) {
    uint32_t s = (uint32_t)__cvta_generic_to_shared(smem);
    asm volatile("cp.async.cg.shared.global [%0], [%1], 16;" :: "r"(s), "l"(g));
}

// ---------------------------------------------------------------------------
// tf32 tensor-core GEMM: C[m,n] = sum_k A[m,k] * W[n,k]
// Block tile 128x128, K-chunk 16, double-buffered cp.async.
// 8 warps: 2(M) x 4(N), warp tile 64x32 (4x4 m16n8k8 tiles).
// EPI 0: row-major store; EPI 1/2: RoPE scatter to g_Q/g_K; EPI 3: scatter g_V.
// ---------------------------------------------------------------------------
template<int EPI>
__global__ __launch_bounds__(256)
void gemm_tf32_kernel(const float* __restrict__ A, const float* __restrict__ W,
                      float* __restrict__ Cout, const int* __restrict__ pos)
{
    __shared__ float As[2][128][20];
    __shared__ float Ws[2][128][20];

    const int tid = threadIdx.x;
    const int m0 = blockIdx.y * 128;
    const int n0 = blockIdx.x * 128;
    const int w = tid >> 5, lane = tid & 31;
    const int wm = (w & 1) * 64;       // warp M offset in tile
    const int wn = (w >> 1) * 32;      // warp N offset in tile
    const int r = lane >> 2, c = lane & 3;

    float acc[4][4][4];
#pragma unroll
    for (int mt = 0; mt < 4; mt++)
#pragma unroll
        for (int nt = 0; nt < 4; nt++)
#pragma unroll
            for (int i = 0; i < 4; i++) acc[mt][nt][i] = 0.f;

    // stage loader: 128 rows x 16 floats per tile = 512 float4; 2 per thread per tile
    auto load_stage = [&](int buf, int kt) {
        int k0 = kt * 16;
#pragma unroll
        for (int i = 0; i < 2; i++) {
            int idx = tid + i * 256;       // 0..511
            int row = idx >> 2;            // 0..127
            int kc = (idx & 3) * 4;        // 0,4,8,12
            cp16(&As[buf][row][kc], A + (size_t)(m0 + row) * DD + k0 + kc);
            cp16(&Ws[buf][row][kc], W + (size_t)(n0 + row) * DD + k0 + kc);
        }
    };

    load_stage(0, 0);
    asm volatile("cp.async.commit_group;");

    int buf = 0;
    const int KT = DD / 16;  // 64
    for (int kt = 0; kt < KT; kt++) {
        if (kt + 1 < KT) {
            load_stage(buf ^ 1, kt + 1);
            asm volatile("cp.async.commit_group;");
            asm volatile("cp.async.wait_group 1;");
        } else {
            asm volatile("cp.async.wait_group 0;");
        }
        __syncthreads();

#pragma unroll
        for (int kk = 0; kk < 2; kk++) {
            uint32_t af[4][4];
#pragma unroll
            for (int mt = 0; mt < 4; mt++) {
                int row = wm + mt * 16 + r;
                af[mt][0] = f2tf(As[buf][row][kk * 8 + c]);
                af[mt][1] = f2tf(As[buf][row + 8][kk * 8 + c]);
                af[mt][2] = f2tf(As[buf][row][kk * 8 + c + 4]);
                af[mt][3] = f2tf(As[buf][row + 8][kk * 8 + c + 4]);
            }
            uint32_t bf[4][2];
#pragma unroll
            for (int nt = 0; nt < 4; nt++) {
                int col = wn + nt * 8 + r;
                bf[nt][0] = f2tf(Ws[buf][col][kk * 8 + c]);
                bf[nt][1] = f2tf(Ws[buf][col][kk * 8 + c + 4]);
            }
#pragma unroll
            for (int mt = 0; mt < 4; mt++)
#pragma unroll
                for (int nt = 0; nt < 4; nt++)
                    mma_tf32(acc[mt][nt], af[mt], bf[nt]);
        }
        __syncthreads();
        buf ^= 1;
    }

    // ---------------- epilogue ----------------
    const float LN_TH_OVER = 9.210340372f / 64.0f;  // ln(10000)/64
#pragma unroll
    for (int mt = 0; mt < 4; mt++) {
#pragma unroll
        for (int nt = 0; nt < 4; nt++) {
            int n = n0 + wn + nt * 8 + c * 2;       // even column
#pragma unroll
            for (int half = 0; half < 2; half++) {  // c0,c1 then c2,c3
                int m = m0 + wm + mt * 16 + r + half * 8;
                float v0 = acc[mt][nt][half * 2];
                float v1 = acc[mt][nt][half * 2 + 1];
                if (EPI == 0) {
                    *(float2*)(Cout + (size_t)m * DD + n) = make_float2(v0, v1);
                } else if (EPI == 3) {
                    int b = m >> 11, s = m & (SS - 1);
                    int h = n >> 6, dk = n & 63;
                    float* dst = g_V + (((size_t)(b * HH + h) * SS + s) * DKK + dk);
                    *(float2*)dst = make_float2(v0, v1);
                } else {
                    int b = m >> 11, s = m & (SS - 1);
                    int h = n >> 6, dk = n & 63;  // even
                    float p = (float)pos[s];
                    float inv = expf(-(float)dk * LN_TH_OVER);
                    float sn, cs;
                    sincosf(p * inv, &sn, &cs);
                    float o0 = v0 * cs - v1 * sn;
                    float o1 = v0 * sn + v1 * cs;
                    float* dst = (EPI == 1 ? g_Q : g_K)
                               + (((size_t)(b * HH + h) * SS + s) * DKK + dk);
                    *(float2*)dst = make_float2(o0, o1);
                }
            }
        }
    }
}

// ---------------------------------------------------------------------------
// Flash attention, fp32, causal. Q-tile 128, KV-tile 64, Dk=64. (unchanged)
// ---------------------------------------------------------------------------
__global__ __launch_bounds__(256)
void attn_kernel()
{
    extern __shared__ float sm[];
    float* Qs = sm;                    // 64*132
    float* Ks = Qs + 64 * 132;         // 64*68
    float* Vs = Ks + 64 * 68;          // 64*68
    float* Ps = Vs + 64 * 68;          // 64*132

    const int qt = blockIdx.x;
    const int h  = blockIdx.y;
    const int b  = blockIdx.z;
    const int tid = threadIdx.x;
    const int ty = tid >> 4, tx = tid & 15;
    const int row0 = ty * 8;
    const int c0 = tx * 4;

    const float* Q = g_Q + (size_t)(b * HH + h) * SS * DKK;
    const float* K = g_K + (size_t)(b * HH + h) * SS * DKK;
    const float* V = g_V + (size_t)(b * HH + h) * SS * DKK;

#pragma unroll
    for (int i = 0; i < 8; i++) {
        int idx = tid + i * 256;
        int rr = idx >> 4;
        int k4 = (idx & 15) * 4;
        float4 v = *(const float4*)(Q + (qt * 128 + rr) * DKK + k4);
        Qs[(k4 + 0) * 132 + rr] = v.x * 0.125f;
        Qs[(k4 + 1) * 132 + rr] = v.y * 0.125f;
        Qs[(k4 + 2) * 132 + rr] = v.z * 0.125f;
        Qs[(k4 + 3) * 132 + rr] = v.w * 0.125f;
    }

    float mstate[8], lstate[8], accO[8][4];
#pragma unroll
    for (int i = 0; i < 8; i++) {
        mstate[i] = -1e30f;
        lstate[i] = 0.f;
#pragma unroll
        for (int j = 0; j < 4; j++) accO[i][j] = 0.f;
    }
    __syncthreads();

    const int ktmax = qt * 2 + 1;
    for (int kt = 0; kt <= ktmax; kt++) {
#pragma unroll
        for (int i = 0; i < 4; i++) {
            int idx = tid + i * 256;
            int rr = idx >> 4;
            int k4 = (idx & 15) * 4;
            float4 kv = *(const float4*)(K + (kt * 64 + rr) * DKK + k4);
            Ks[(k4 + 0) * 68 + rr] = kv.x;
            Ks[(k4 + 1) * 68 + rr] = kv.y;
            Ks[(k4 + 2) * 68 + rr] = kv.z;
            Ks[(k4 + 3) * 68 + rr] = kv.w;
            float4 vv = *(const float4*)(V + (kt * 64 + rr) * DKK + k4);
            *(float4*)&Vs[rr * 68 + k4] = vv;
        }
        __syncthreads();

        float sacc[8][4];
#pragma unroll
        for (int i = 0; i < 8; i++)
#pragma unroll
            for (int j = 0; j < 4; j++) sacc[i][j] = 0.f;

#pragma unroll 8
        for (int d = 0; d < 64; d++) {
            float4 a0 = *(const float4*)&Qs[d * 132 + row0];
            float4 a1 = *(const float4*)&Qs[d * 132 + row0 + 4];
            float4 bb = *(const float4*)&Ks[d * 68 + c0];
            float a[8] = {a0.x, a0.y, a0.z, a0.w, a1.x, a1.y, a1.z, a1.w};
            float bv[4] = {bb.x, bb.y, bb.z, bb.w};
#pragma unroll
            for (int i = 0; i < 8; i++)
#pragma unroll
                for (int j = 0; j < 4; j++)
                    sacc[i][j] = fmaf(a[i], bv[j], sacc[i][j]);
        }

        if (kt >= qt * 2) {
#pragma unroll
            for (int i = 0; i < 8; i++) {
                int qg = qt * 128 + row0 + i;
#pragma unroll
                for (int j = 0; j < 4; j++) {
                    int cg = kt * 64 + c0 + j;
                    if (cg > qg) sacc[i][j] = -1e30f;
                }
            }
        }

        float pvals[8][4];
#pragma unroll
        for (int i = 0; i < 8; i++) {
            float mloc = sacc[i][0];
            mloc = fmaxf(mloc, sacc[i][1]);
            mloc = fmaxf(mloc, sacc[i][2]);
            mloc = fmaxf(mloc, sacc[i][3]);
#pragma unroll
            for (int off = 1; off < 16; off <<= 1)
                mloc = fmaxf(mloc, __shfl_xor_sync(0xffffffffu, mloc, off));
            float mnew = fmaxf(mstate[i], mloc);
            float sf = __expf(mstate[i] - mnew);
            float rs = 0.f;
#pragma unroll
            for (int j = 0; j < 4; j++) {
                float pv = __expf(sacc[i][j] - mnew);
                pvals[i][j] = pv;
                rs += pv;
            }
#pragma unroll
            for (int off = 1; off < 16; off <<= 1)
                rs += __shfl_xor_sync(0xffffffffu, rs, off);
            lstate[i] = lstate[i] * sf + rs;
            mstate[i] = mnew;
#pragma unroll
            for (int j = 0; j < 4; j++) accO[i][j] *= sf;
        }

#pragma unroll
        for (int i = 0; i < 8; i++)
#pragma unroll
            for (int j = 0; j < 4; j++)
                Ps[(c0 + j) * 132 + row0 + i] = pvals[i][j];
        __syncthreads();

#pragma unroll 8
        for (int cc = 0; cc < 64; cc++) {
            float4 a0 = *(const float4*)&Ps[cc * 132 + row0];
            float4 a1 = *(const float4*)&Ps[cc * 132 + row0 + 4];
            float4 bb = *(const float4*)&Vs[cc * 68 + c0];
            float a[8] = {a0.x, a0.y, a0.z, a0.w, a1.x, a1.y, a1.z, a1.w};
            float bv[4] = {bb.x, bb.y, bb.z, bb.w};
#pragma unroll
            for (int i = 0; i < 8; i++)
#pragma unroll
                for (int j = 0; j < 4; j++)
                    accO[i][j] = fmaf(a[i], bv[j], accO[i][j]);
        }
        __syncthreads();
    }

#pragma unroll
    for (int i = 0; i < 8; i++) {
        float inv_l = 1.f / lstate[i];
        int s = qt * 128 + row0 + i;
        float4 v = make_float4(accO[i][0] * inv_l, accO[i][1] * inv_l,
                               accO[i][2] * inv_l, accO[i][3] * inv_l);
        *(float4*)(g_Ctx + (size_t)(b * SS + s) * DD + h * 64 + c0) = v;
    }
}

// ---------------------------------------------------------------------------
extern "C" void kernel_launch(void* const* d_in, const int* in_sizes, int n_in,
                              void* d_out, int out_size)
{
    const float* x  = (const float*)d_in[0];
    const float* Wq = (const float*)d_in[1];
    const float* Wk = (const float*)d_in[2];
    const float* Wv = (const float*)d_in[3];
    const float* Wo = (const float*)d_in[4];
    const int* pos  = (const int*)d_in[5];
    float* out = (float*)d_out;

    void* ctx_ptr = nullptr;
    cudaGetSymbolAddress(&ctx_ptr, g_Ctx);

    dim3 ggrid(DD / 128, M_TOTAL / 128);   // 8 x 64

    gemm_tf32_kernel<1><<<ggrid, 256>>>(x, Wq, nullptr, pos);
    gemm_tf32_kernel<2><<<ggrid, 256>>>(x, Wk, nullptr, pos);
    gemm_tf32_kernel<3><<<ggrid, 256>>>(x, Wv, nullptr, pos);

    static int smem_set = 0;
    const int ATTN_SMEM = (64 * 132 + 64 * 68 + 64 * 68 + 64 * 132) * 4; // 102400
    if (!smem_set) {
        cudaFuncSetAttribute(attn_kernel,
                             cudaFuncAttributeMaxDynamicSharedMemorySize,
                             ATTN_SMEM);
        smem_set = 1;
    }
    dim3 agrid(SS / 128, HH, BB);
    attn_kernel<<<agrid, 256, ATTN_SMEM>>>();

    gemm_tf32_kernel<0><<<ggrid, 256>>>((const float*)ctx_ptr, Wo, out, pos);
}

// round 3
// speedup vs baseline: 3.4329x; 2.0448x over previous
#include <cuda_runtime.h>
#include <cuda_fp16.h>
#include <math.h>
#include <stdint.h>

#define BB 4
#define SS 2048
#define DD 1024
#define HH 16
#define DKK 64
#define M_TOTAL (BB*SS)

// Scratch (device globals; allocation-free per harness rules)
__device__ __half g_Qh[BB*HH*SS*DKK];   // [b,h,s,d], pre-scaled by 1/8
__device__ __half g_Kh[BB*HH*SS*DKK];   // [b,h,s,d]
__device__ __half g_Vt[BB*HH*DKK*SS];   // [b,h,d,s]  (transposed V)
__device__ float  g_Ctx[BB*SS*DD];

// ---------------------------------------------------------------------------
// helpers
// ---------------------------------------------------------------------------
__device__ __forceinline__ uint32_t f2tf(float x) {
    uint32_t r;
    asm("cvt.rna.tf32.f32 %0, %1;" : "=r"(r) : "f"(x));
    return r;
}

__device__ __forceinline__ void mma_tf32(float* c, const uint32_t* a, const uint32_t* b) {
    asm volatile(
        "mma.sync.aligned.m16n8k8.row.col.f32.tf32.tf32.f32 "
        "{%0,%1,%2,%3},{%4,%5,%6,%7},{%8,%9},{%0,%1,%2,%3};"
        : "+f"(c[0]), "+f"(c[1]), "+f"(c[2]), "+f"(c[3])
        : "r"(a[0]), "r"(a[1]), "r"(a[2]), "r"(a[3]), "r"(b[0]), "r"(b[1]));
}

__device__ __forceinline__ void mma_f16(float* c, const uint32_t* a,
                                        uint32_t b0, uint32_t b1) {
    asm volatile(
        "mma.sync.aligned.m16n8k16.row.col.f32.f16.f16.f32 "
        "{%0,%1,%2,%3},{%4,%5,%6,%7},{%8,%9},{%0,%1,%2,%3};"
        : "+f"(c[0]), "+f"(c[1]), "+f"(c[2]), "+f"(c[3])
        : "r"(a[0]), "r"(a[1]), "r"(a[2]), "r"(a[3]), "r"(b0), "r"(b1));
}

__device__ __forceinline__ void cp16(void* smem, const void* g) {
    uint32_t s = (uint32_t)__cvta_generic_to_shared(smem);
    asm volatile("cp.async.cg.shared.global [%0], [%1], 16;" :: "r"(s), "l"(g));
}

// swizzled 32-bit shared load: rows are 128B, 16B chunks XORed by row%8
__device__ __forceinline__ uint32_t ldswz(const char* base, int row, int bo) {
    int chunk = bo >> 4, intra = bo & 15;
    return *(const uint32_t*)(base + row * 128 + ((chunk ^ (row & 7)) << 4) + intra);
}

__device__ __forceinline__ uint32_t packh2(float lo, float hi) {
    __half2 h = __floats2half2_rn(lo, hi);
    return *(uint32_t*)&h;
}

// ---------------------------------------------------------------------------
// tf32 tensor-core GEMM: C[m,n] = sum_k A[m,k] * W[n,k]
// EPI 0: fp32 row-major store; EPI 1: RoPE*0.125 -> g_Qh; EPI 2: RoPE -> g_Kh;
// EPI 3: -> g_Vt transposed.
// ---------------------------------------------------------------------------
template<int EPI>
__global__ __launch_bounds__(256)
void gemm_tf32_kernel(const float* __restrict__ A, const float* __restrict__ W,
                      float* __restrict__ Cout, const int* __restrict__ pos)
{
    __shared__ float As[2][128][20];
    __shared__ float Ws[2][128][20];

    const int tid = threadIdx.x;
    const int m0 = blockIdx.y * 128;
    const int n0 = blockIdx.x * 128;
    const int w = tid >> 5, lane = tid & 31;
    const int wm = (w & 1) * 64;
    const int wn = (w >> 1) * 32;
    const int r = lane >> 2, c = lane & 3;

    float acc[4][4][4];
#pragma unroll
    for (int mt = 0; mt < 4; mt++)
#pragma unroll
        for (int nt = 0; nt < 4; nt++)
#pragma unroll
            for (int i = 0; i < 4; i++) acc[mt][nt][i] = 0.f;

    auto load_stage = [&](int buf, int kt) {
        int k0 = kt * 16;
#pragma unroll
        for (int i = 0; i < 2; i++) {
            int idx = tid + i * 256;
            int row = idx >> 2;
            int kc = (idx & 3) * 4;
            cp16(&As[buf][row][kc], A + (size_t)(m0 + row) * DD + k0 + kc);
            cp16(&Ws[buf][row][kc], W + (size_t)(n0 + row) * DD + k0 + kc);
        }
    };

    load_stage(0, 0);
    asm volatile("cp.async.commit_group;");

    int buf = 0;
    const int KT = DD / 16;
    for (int kt = 0; kt < KT; kt++) {
        if (kt + 1 < KT) {
            load_stage(buf ^ 1, kt + 1);
            asm volatile("cp.async.commit_group;");
            asm volatile("cp.async.wait_group 1;");
        } else {
            asm volatile("cp.async.wait_group 0;");
        }
        __syncthreads();

#pragma unroll
        for (int kk = 0; kk < 2; kk++) {
            uint32_t af[4][4];
#pragma unroll
            for (int mt = 0; mt < 4; mt++) {
                int row = wm + mt * 16 + r;
                af[mt][0] = f2tf(As[buf][row][kk * 8 + c]);
                af[mt][1] = f2tf(As[buf][row + 8][kk * 8 + c]);
                af[mt][2] = f2tf(As[buf][row][kk * 8 + c + 4]);
                af[mt][3] = f2tf(As[buf][row + 8][kk * 8 + c + 4]);
            }
            uint32_t bf[4][2];
#pragma unroll
            for (int nt = 0; nt < 4; nt++) {
                int col = wn + nt * 8 + r;
                bf[nt][0] = f2tf(Ws[buf][col][kk * 8 + c]);
                bf[nt][1] = f2tf(Ws[buf][col][kk * 8 + c + 4]);
            }
#pragma unroll
            for (int mt = 0; mt < 4; mt++)
#pragma unroll
                for (int nt = 0; nt < 4; nt++)
                    mma_tf32(acc[mt][nt], af[mt], bf[nt]);
        }
        __syncthreads();
        buf ^= 1;
    }

    // ---------------- epilogue ----------------
    const float LN_TH_OVER = 9.210340372f / 64.0f;  // ln(10000)/64
#pragma unroll
    for (int mt = 0; mt < 4; mt++) {
#pragma unroll
        for (int nt = 0; nt < 4; nt++) {
            int n = n0 + wn + nt * 8 + c * 2;       // even column
#pragma unroll
            for (int half = 0; half < 2; half++) {
                int m = m0 + wm + mt * 16 + r + half * 8;
                float v0 = acc[mt][nt][half * 2];
                float v1 = acc[mt][nt][half * 2 + 1];
                if (EPI == 0) {
                    *(float2*)(Cout + (size_t)m * DD + n) = make_float2(v0, v1);
                } else if (EPI == 3) {
                    int b = m >> 11, s = m & (SS - 1);
                    int h = n >> 6, dk = n & 63;
                    __half* dst = g_Vt + ((size_t)(b * HH + h) * DKK + dk) * SS + s;
                    dst[0]  = __float2half_rn(v0);
                    dst[SS] = __float2half_rn(v1);
                } else {
                    int b = m >> 11, s = m & (SS - 1);
                    int h = n >> 6, dk = n & 63;  // even
                    float p = (float)pos[s];
                    float inv = expf(-(float)dk * LN_TH_OVER);
                    float sn, cs;
                    sincosf(p * inv, &sn, &cs);
                    float o0 = v0 * cs - v1 * sn;
                    float o1 = v0 * sn + v1 * cs;
                    if (EPI == 1) { o0 *= 0.125f; o1 *= 0.125f; }
                    __half* dst = (EPI == 1 ? g_Qh : g_Kh)
                               + (((size_t)(b * HH + h) * SS + s) * DKK + dk);
                    *(uint32_t*)dst = packh2(o0, o1);
                }
            }
        }
    }
}

// ---------------------------------------------------------------------------
// FlashAttention-2 style fp16 tensor-core attention.
// Block: 128 Q rows, 8 warps (16 rows each). KV tile 64. Causal.
// K smem: [kv][d] natural; V smem: [d][kv] (g_Vt already transposed).
// 128B rows with XOR-16B swizzle, cp.async double buffered.
// ---------------------------------------------------------------------------
__global__ __launch_bounds__(256, 2)
void attn_kernel()
{
    __shared__ __align__(16) char sK[2][64 * 128];
    __shared__ __align__(16) char sV[2][64 * 128];

    const int qt = (int)gridDim.x - 1 - (int)blockIdx.x;  // heavy tiles first
    const int h  = blockIdx.y;
    const int b  = blockIdx.z;
    const int tid = threadIdx.x;
    const int w = tid >> 5, lane = tid & 31;
    const int g = lane >> 2, c = lane & 3;
    const int q0w = qt * 128 + w * 16;    // this warp's first Q row

    const __half* Qbh = g_Qh + (size_t)(b * HH + h) * SS * DKK;
    const __half* Kbh = g_Kh + (size_t)(b * HH + h) * SS * DKK;
    const __half* Vbh = g_Vt + (size_t)(b * HH + h) * DKK * SS;

    // Q fragments in registers for the whole kernel (already scaled by 1/8)
    uint32_t qreg[4][4];
#pragma unroll
    for (int kk = 0; kk < 4; kk++) {
        qreg[kk][0] = *(const uint32_t*)(Qbh + (q0w + g) * DKK + 16 * kk + 2 * c);
        qreg[kk][1] = *(const uint32_t*)(Qbh + (q0w + g + 8) * DKK + 16 * kk + 2 * c);
        qreg[kk][2] = *(const uint32_t*)(Qbh + (q0w + g) * DKK + 16 * kk + 2 * c + 8);
        qreg[kk][3] = *(const uint32_t*)(Qbh + (q0w + g + 8) * DKK + 16 * kk + 2 * c + 8);
    }

    float Oc[8][4];
#pragma unroll
    for (int n = 0; n < 8; n++)
#pragma unroll
        for (int i = 0; i < 4; i++) Oc[n][i] = 0.f;
    float mrow[2] = {-1e30f, -1e30f};
    float lrow[2] = {0.f, 0.f};

    auto load_kv = [&](int bufi, int kt) {
        int kv0 = kt * 64;
#pragma unroll
        for (int i = 0; i < 2; i++) {
            int idx = tid + i * 256;          // 0..511
            int r = idx >> 3;                 // 0..63
            int ch = idx & 7;                 // 16B chunk
            int dst = r * 128 + ((ch ^ (r & 7)) << 4);
            cp16(sK[bufi] + dst, Kbh + (size_t)(kv0 + r) * DKK + ch * 8);
            cp16(sV[bufi] + dst, Vbh + (size_t)r * SS + kv0 + ch * 8);
        }
    };

    const int ktmax = qt * 2 + 1;
    load_kv(0, 0);
    asm volatile("cp.async.commit_group;");

    int buf = 0;
    for (int kt = 0; kt <= ktmax; kt++) {
        if (kt < ktmax) {
            load_kv(buf ^ 1, kt + 1);
            asm volatile("cp.async.commit_group;");
            asm volatile("cp.async.wait_group 1;");
        } else {
            asm volatile("cp.async.wait_group 0;");
        }
        __syncthreads();

        const int kv0 = kt * 64;

        // ---- S = Q K^T ----
        float Sc[8][4];
#pragma unroll
        for (int n = 0; n < 8; n++)
#pragma unroll
            for (int i = 0; i < 4; i++) Sc[n][i] = 0.f;

#pragma unroll
        for (int n = 0; n < 8; n++) {
#pragma unroll
            for (int kk = 0; kk < 4; kk++) {
                uint32_t b0 = ldswz(sK[buf], n * 8 + g, 32 * kk + 4 * c);
                uint32_t b1 = ldswz(sK[buf], n * 8 + g, 32 * kk + 16 + 4 * c);
                mma_f16(Sc[n], qreg[kk], b0, b1);
            }
        }

        // ---- causal mask (only on diagonal-touching tiles for this warp) ----
        if (kv0 + 63 > q0w) {
            int r0 = q0w + g, r1 = q0w + g + 8;
#pragma unroll
            for (int n = 0; n < 8; n++) {
                int col = kv0 + n * 8 + 2 * c;
                if (col > r0)     Sc[n][0] = -1e30f;
                if (col + 1 > r0) Sc[n][1] = -1e30f;
                if (col > r1)     Sc[n][2] = -1e30f;
                if (col + 1 > r1) Sc[n][3] = -1e30f;
            }
        }

        // ---- online softmax (rows g and g+8; quad reduce over lanes) ----
        float mx0 = Sc[0][0], mx1 = Sc[0][2];
#pragma unroll
        for (int n = 0; n < 8; n++) {
            mx0 = fmaxf(mx0, fmaxf(Sc[n][0], Sc[n][1]));
            mx1 = fmaxf(mx1, fmaxf(Sc[n][2], Sc[n][3]));
        }
        mx0 = fmaxf(mx0, __shfl_xor_sync(0xffffffffu, mx0, 1));
        mx0 = fmaxf(mx0, __shfl_xor_sync(0xffffffffu, mx0, 2));
        mx1 = fmaxf(mx1, __shfl_xor_sync(0xffffffffu, mx1, 1));
        mx1 = fmaxf(mx1, __shfl_xor_sync(0xffffffffu, mx1, 2));

        float mn0 = fmaxf(mrow[0], mx0);
        float mn1 = fmaxf(mrow[1], mx1);
        float a0 = __expf(mrow[0] - mn0);
        float a1 = __expf(mrow[1] - mn1);

        float rs0 = 0.f, rs1 = 0.f;
#pragma unroll
        for (int n = 0; n < 8; n++) {
            Sc[n][0] = __expf(Sc[n][0] - mn0);
            Sc[n][1] = __expf(Sc[n][1] - mn0);
            Sc[n][2] = __expf(Sc[n][2] - mn1);
            Sc[n][3] = __expf(Sc[n][3] - mn1);
            rs0 += Sc[n][0] + Sc[n][1];
            rs1 += Sc[n][2] + Sc[n][3];
        }
        rs0 += __shfl_xor_sync(0xffffffffu, rs0, 1);
        rs0 += __shfl_xor_sync(0xffffffffu, rs0, 2);
        rs1 += __shfl_xor_sync(0xffffffffu, rs1, 1);
        rs1 += __shfl_xor_sync(0xffffffffu, rs1, 2);

        lrow[0] = lrow[0] * a0 + rs0;
        lrow[1] = lrow[1] * a1 + rs1;
        mrow[0] = mn0; mrow[1] = mn1;

#pragma unroll
        for (int n = 0; n < 8; n++) {
            Oc[n][0] *= a0; Oc[n][1] *= a0;
            Oc[n][2] *= a1; Oc[n][3] *= a1;
        }

        // ---- pack P into A fragments (C layout == A layout for f16 k16) ----
        uint32_t pa[4][4];
#pragma unroll
        for (int kk = 0; kk < 4; kk++) {
            pa[kk][0] = packh2(Sc[2 * kk][0],     Sc[2 * kk][1]);
            pa[kk][1] = packh2(Sc[2 * kk][2],     Sc[2 * kk][3]);
            pa[kk][2] = packh2(Sc[2 * kk + 1][0], Sc[2 * kk + 1][1]);
            pa[kk][3] = packh2(Sc[2 * kk + 1][2], Sc[2 * kk + 1][3]);
        }

        // ---- O += P V ----
#pragma unroll
        for (int nd = 0; nd < 8; nd++) {
#pragma unroll
            for (int kk = 0; kk < 4; kk++) {
                uint32_t b0 = ldswz(sV[buf], nd * 8 + g, 32 * kk + 4 * c);
                uint32_t b1 = ldswz(sV[buf], nd * 8 + g, 32 * kk + 16 + 4 * c);
                mma_f16(Oc[nd], pa[kk], b0, b1);
            }
        }

        __syncthreads();
        buf ^= 1;
    }

    // ---- finalize, write context fp32 [b,s,D] ----
    float inv0 = 1.f / lrow[0];
    float inv1 = 1.f / lrow[1];
    float* Cb0 = g_Ctx + ((size_t)(b * SS + q0w + g) * DD + h * 64);
    float* Cb1 = g_Ctx + ((size_t)(b * SS + q0w + g + 8) * DD + h * 64);
#pragma unroll
    for (int nd = 0; nd < 8; nd++) {
        int col = nd * 8 + 2 * c;
        *(float2*)(Cb0 + col) = make_float2(Oc[nd][0] * inv0, Oc[nd][1] * inv0);
        *(float2*)(Cb1 + col) = make_float2(Oc[nd][2] * inv1, Oc[nd][3] * inv1);
    }
}

// ---------------------------------------------------------------------------
extern "C" void kernel_launch(void* const* d_in, const int* in_sizes, int n_in,
                              void* d_out, int out_size)
{
    const float* x  = (const float*)d_in[0];
    const float* Wq = (const float*)d_in[1];
    const float* Wk = (const float*)d_in[2];
    const float* Wv = (const float*)d_in[3];
    const float* Wo = (const float*)d_in[4];
    const int* pos  = (const int*)d_in[5];
    float* out = (float*)d_out;

    void* ctx_ptr = nullptr;
    cudaGetSymbolAddress(&ctx_ptr, g_Ctx);

    dim3 ggrid(DD / 128, M_TOTAL / 128);   // 8 x 64

    gemm_tf32_kernel<1><<<ggrid, 256>>>(x, Wq, nullptr, pos);
    gemm_tf32_kernel<2><<<ggrid, 256>>>(x, Wk, nullptr, pos);
    gemm_tf32_kernel<3><<<ggrid, 256>>>(x, Wv, nullptr, pos);

    dim3 agrid(SS / 128, HH, BB);
    attn_kernel<<<agrid, 256>>>();

    gemm_tf32_kernel<0><<<ggrid, 256>>>((const float*)ctx_ptr, Wo, out, pos);
}